// round 7
// baseline (speedup 1.0000x reference)
#include <cuda_runtime.h>
#include <cuda_fp16.h>
#include <cstdint>

// ============================================================================
// BBoxHead as one fp16 legacy-HMMA GEMM (mma.sync.m16n8k16; compute_103 target
// has no tcgen05). C[8192,448] = A[8192,12544] x W[448,12544]^T, fp32 acc.
//   cols 0..80   -> cls head (+b_cls):  out[m*81 + n]
//   cols 81..404 -> reg head (+b_reg):  out[8192*81 + m*324 + (n-81)]
//   cols 405..447 = zero pad (discarded)
// Round-7 vs round-6 (302us): split N into two 224-col halves -> grid 256,
// 8 warps/CTA (2Mx4N, warp tile 32x56), __launch_bounds__(256,2): 2 CTAs/SM
// (smem 110KB/CTA, ~128 regs/thread) so each CTA's barrier/ramp exposure
// (~800 cyc/chunk, the round-6 residual) hides behind the peer CTA's compute.
// ============================================================================

#define KDIM  12544
#define MDIM  8192
#define NCLS  81
#define NREG  324
#define NTOT  405
#define NPAD  448
#define BM    64
#define BN    224
#define BK    64
#define NCHUNK 196            // 12544 / 64
#define NTHREADS 256

#define A_STAGE 8192          // 64 rows x 128B
#define B_STAGE 28672         // 224 rows x 128B
#define OFF_BIAS 0
#define OFF_A    2048
#define OFF_B    (OFF_A + 3 * A_STAGE)        // 26624
#define SMEM_TOTAL (OFF_B + 3 * B_STAGE)      // 112640  (2x <= 227KB carveout)

__device__ __half g_Wh[(size_t)NPAD * KDIM];  // 11.2 MB fp16 W scratch

// ---------------- helpers ----------------
__device__ __forceinline__ uint32_t smem_u32(const void* p) {
    uint32_t a;
    asm("{ .reg .u64 t; cvta.to.shared.u64 t, %1; cvt.u32.u64 %0, t; }" : "=r"(a) : "l"(p));
    return a;
}
// 128B rows, 8 x 16B chunks per row; chunk XOR row&7 keeps both the 16B store
// phases and all ldmatrix read phases bank-conflict-free.
__device__ __forceinline__ uint32_t swz8(uint32_t row, uint32_t q) {
    return row * 128u + ((q ^ (row & 7u)) << 4);
}
__device__ __forceinline__ void cpa16(uint32_t dst, const void* src) {
    asm volatile("cp.async.cg.shared.global [%0], [%1], 16;" :: "r"(dst), "l"(src) : "memory");
}
#define CP_COMMIT() asm volatile("cp.async.commit_group;" ::: "memory")
#define CP_WAIT1()  asm volatile("cp.async.wait_group 1;" ::: "memory")

__device__ __forceinline__ void ldsm4(uint32_t* r, uint32_t addr) {
    asm volatile("ldmatrix.sync.aligned.m8n8.x4.shared.b16 {%0,%1,%2,%3}, [%4];"
        : "=r"(r[0]), "=r"(r[1]), "=r"(r[2]), "=r"(r[3]) : "r"(addr));
}
__device__ __forceinline__ void ldsm2(uint32_t* r, uint32_t addr) {
    asm volatile("ldmatrix.sync.aligned.m8n8.x2.shared.b16 {%0,%1}, [%2];"
        : "=r"(r[0]), "=r"(r[1]) : "r"(addr));
}
__device__ __forceinline__ void mma16816(float* c, const uint32_t* a, const uint32_t* b) {
    asm volatile(
        "mma.sync.aligned.m16n8k16.row.col.f32.f16.f16.f32 "
        "{%0,%1,%2,%3}, {%4,%5,%6,%7}, {%8,%9}, {%0,%1,%2,%3};"
        : "+f"(c[0]), "+f"(c[1]), "+f"(c[2]), "+f"(c[3])
        : "r"(a[0]), "r"(a[1]), "r"(a[2]), "r"(a[3]), "r"(b[0]), "r"(b[1]));
}
__device__ __forceinline__ uint32_t packh2(float lo, float hi) {
    uint32_t r;
    asm("cvt.rn.f16x2.f32 %0, %1, %2;" : "=r"(r) : "f"(hi), "f"(lo));
    return r;
}

// ---------------- W fp32 -> fp16 pre-kernel (rows >= 405 zeroed) ----------------
__global__ void wconv_kernel(const float* __restrict__ Wc, const float* __restrict__ Wr) {
    int row = blockIdx.y;
    int col = (blockIdx.x * 256 + threadIdx.x) * 4;
    if (col >= KDIM) return;
    float4 v = make_float4(0.f, 0.f, 0.f, 0.f);
    if (row < NCLS)      v = *reinterpret_cast<const float4*>(Wc + (size_t)row * KDIM + col);
    else if (row < NTOT) v = *reinterpret_cast<const float4*>(Wr + (size_t)(row - NCLS) * KDIM + col);
    *reinterpret_cast<uint2*>(&g_Wh[(size_t)row * KDIM + col]) =
        make_uint2(packh2(v.x, v.y), packh2(v.z, v.w));
}

// ---------------- main GEMM kernel ----------------
__global__ __launch_bounds__(NTHREADS, 2)
void bbox_head_mma(const float* __restrict__ A,
                   const float* __restrict__ bc,
                   const float* __restrict__ br,
                   float* __restrict__ out)
{
    extern __shared__ char smem[];
    const uint32_t sb = smem_u32(smem);
    const int tid   = threadIdx.x;
    const int lane  = tid & 31;
    const int wid   = tid >> 5;
    const int warpM = wid & 1;          // 0..1  (32-row halves of BM=64)
    const int warpN = wid >> 1;         // 0..3  (56-col slices of BN=224)
    const int mBlock = blockIdx.x * BM;
    const int nBase  = blockIdx.y * BN; // 0 or 224
    float* bias_sm = reinterpret_cast<float*>(smem + OFF_BIAS);

    for (int j = tid; j < BN; j += NTHREADS) {
        int n = nBase + j;
        bias_sm[j] = (n < NCLS) ? bc[n] : ((n < NTOT) ? br[n - NCLS] : 0.f);
    }

    // A loader: thread owns row (tid>>2), chunks q0=2*(tid&3), q0+1 (32B fp16)
    const int ar = tid >> 2;            // 0..63
    const int aq = (tid & 3) * 2;       // 0,2,4,6
    float4 abuf[4];

    float acc[2][7][4];
    #pragma unroll
    for (int i = 0; i < 2; i++)
        #pragma unroll
        for (int j = 0; j < 7; j++)
            #pragma unroll
            for (int v = 0; v < 4; v++) acc[i][j][v] = 0.f;

#define LDG_A(K0) do { \
        const float* _p = A + (size_t)(mBlock + ar) * KDIM + (K0) + aq * 8; \
        abuf[0] = *reinterpret_cast<const float4*>(_p); \
        abuf[1] = *reinterpret_cast<const float4*>(_p + 4); \
        abuf[2] = *reinterpret_cast<const float4*>(_p + 8); \
        abuf[3] = *reinterpret_cast<const float4*>(_p + 12); } while (0)

#define STS_A(S) do { \
        uint4 _v0 = make_uint4(packh2(abuf[0].x, abuf[0].y), packh2(abuf[0].z, abuf[0].w), \
                               packh2(abuf[1].x, abuf[1].y), packh2(abuf[1].z, abuf[1].w)); \
        uint4 _v1 = make_uint4(packh2(abuf[2].x, abuf[2].y), packh2(abuf[2].z, abuf[2].w), \
                               packh2(abuf[3].x, abuf[3].y), packh2(abuf[3].z, abuf[3].w)); \
        *reinterpret_cast<uint4*>(smem + OFF_A + (S) * A_STAGE + swz8(ar, aq)) = _v0; \
        *reinterpret_cast<uint4*>(smem + OFF_A + (S) * A_STAGE + swz8(ar, aq + 1)) = _v1; } while (0)

#define CP_B(K0, S) do { \
        _Pragma("unroll") \
        for (int _i = 0; _i < 7; _i++) { \
            int _idx = tid + _i * NTHREADS; /* 0..1791 = 224 rows x 8 chunks */ \
            int _row = _idx >> 3, _q = _idx & 7; \
            cpa16(sb + OFF_B + (S) * B_STAGE + swz8(_row, _q), \
                  g_Wh + (size_t)(nBase + _row) * KDIM + (K0) + _q * 8); } } while (0)

    // ---- prologue ----
    LDG_A(0);
    CP_B(0, 0); CP_COMMIT();
    STS_A(0);
    LDG_A(BK);
    CP_B(BK, 1); CP_COMMIT();

    // ---- main loop ----
    for (int k = 0; k < NCHUNK; k++) {
        CP_WAIT1();
        __syncthreads();

        if (k + 1 < NCHUNK) STS_A((k + 1) % 3);
        if (k + 2 < NCHUNK) { LDG_A((k + 2) * BK); CP_B((k + 2) * BK, (k + 2) % 3); }
        CP_COMMIT();

        const uint32_t aS = sb + OFF_A + (k % 3) * A_STAGE;
        const uint32_t bS = sb + OFF_B + (k % 3) * B_STAGE;

        #pragma unroll
        for (int kt = 0; kt < 4; kt++) {
            uint32_t afrag[2][4];
            #pragma unroll
            for (int msub = 0; msub < 2; msub++) {
                uint32_t row = warpM * 32 + msub * 16 + ((lane >> 3) & 1) * 8 + (lane & 7);
                uint32_t q   = kt * 2 + (lane >> 4);
                ldsm4(afrag[msub], aS + swz8(row, q));
            }
            uint32_t bfrag[7][2];
            #pragma unroll
            for (int p = 0; p < 3; p++) {
                uint32_t row = warpN * 56 + p * 16 + (lane >> 4) * 8 + (lane & 7);
                uint32_t q   = kt * 2 + ((lane >> 3) & 1);
                uint32_t r4[4];
                ldsm4(r4, bS + swz8(row, q));
                bfrag[2 * p][0] = r4[0]; bfrag[2 * p][1] = r4[1];
                bfrag[2 * p + 1][0] = r4[2]; bfrag[2 * p + 1][1] = r4[3];
            }
            {
                uint32_t row = warpN * 56 + 48 + (lane & 7);
                uint32_t q   = kt * 2 + ((lane >> 3) & 1);
                ldsm2(bfrag[6], bS + swz8(row, q));
            }
            #pragma unroll
            for (int mi = 0; mi < 2; mi++)
                #pragma unroll
                for (int ni = 0; ni < 7; ni++)
                    mma16816(acc[mi][ni], afrag[mi], bfrag[ni]);
        }
    }

    // ---- epilogue: bias + split store ----
    const size_t regBase = (size_t)MDIM * NCLS;
    #pragma unroll
    for (int mi = 0; mi < 2; mi++) {
        #pragma unroll
        for (int ni = 0; ni < 7; ni++) {
            int m0 = mBlock + warpM * 32 + mi * 16 + (lane >> 2);
            int nl0 = warpN * 56 + ni * 8 + (lane & 3) * 2;
            #pragma unroll
            for (int v = 0; v < 4; v++) {
                int m = m0 + (v >> 1) * 8;
                int nl = nl0 + (v & 1);
                int n = nBase + nl;
                if (n >= NTOT) continue;
                float val = acc[mi][ni][v] + bias_sm[nl];
                if (n < NCLS) out[(size_t)m * NCLS + n] = val;
                else          out[regBase + (size_t)m * NREG + (n - NCLS)] = val;
            }
        }
    }
}

extern "C" void kernel_launch(void* const* d_in, const int* in_sizes, int n_in,
                              void* d_out, int out_size)
{
    const float* x  = (const float*)d_in[0];
    const float* Wc = (const float*)d_in[1];
    const float* bc = (const float*)d_in[2];
    const float* Wr = (const float*)d_in[3];
    const float* br = (const float*)d_in[4];
    float* out = (float*)d_out;

    cudaFuncSetAttribute(bbox_head_mma, cudaFuncAttributeMaxDynamicSharedMemorySize, SMEM_TOTAL);

    dim3 wgrid((KDIM / 4 + 255) / 256, NPAD);
    wconv_kernel<<<wgrid, 256>>>(Wc, Wr);

    dim3 grid(MDIM / BM, 2);            // 128 x 2 = 256 CTAs
    bbox_head_mma<<<grid, NTHREADS, SMEM_TOTAL>>>(x, bc, br, out);
}

// round 10
// speedup vs baseline: 1.5059x; 1.5059x over previous
#include <cuda_runtime.h>
#include <cuda_fp16.h>
#include <cstdint>

// ============================================================================
// BBoxHead as one fp16 legacy-HMMA GEMM (mma.sync.m16n8k16; compute_103 target
// has no tcgen05). C[8192,448] = A[8192,12544] x W[448,12544]^T, fp32 acc.
//   cols 0..80   -> cls head (+b_cls):  out[m*81 + n]
//   cols 81..404 -> reg head (+b_reg):  out[8192*81 + m*324 + (n-81)]
//   cols 405..447 = zero pad (discarded)
// Round-10 = round-9 resubmission (round-9 bench died on broker infra, kernel
// never ran): round-6 geometry (BK=64, 16 warps 2Mx8N, warp tile 32x56, XOR-8
// swizzle) + per-stage mbarrier full/empty pipelining (3 stages) replacing the
// per-chunk CP_WAIT+__syncthreads lockstep. cp.async completion tracked with
// cp.async.mbarrier.arrive.NOINC (default form is net-zero -> round-8 hang).
// ============================================================================

#define KDIM  12544
#define MDIM  8192
#define NCLS  81
#define NREG  324
#define NTOT  405
#define NPAD  448
#define BM    64
#define BK    64
#define NCHUNK 196            // 12544 / 64
#define NSTAGE 3
#define NTHREADS 512

#define A_STAGE 8192          // 64 rows x 128B
#define B_STAGE 57344         // 448 rows x 128B
#define OFF_BIAS 0            // 448 * 4 = 1792B
#define OFF_MBAR 1792         // 6 mbarriers x 8B
#define OFF_A    2048
#define OFF_B    (OFF_A + NSTAGE * A_STAGE)   // 26624
#define SMEM_TOTAL (OFF_B + NSTAGE * B_STAGE) // 198656

__device__ __half g_Wh[(size_t)NPAD * KDIM];  // 11.2 MB fp16 W scratch

// ---------------- helpers ----------------
__device__ __forceinline__ uint32_t smem_u32(const void* p) {
    uint32_t a;
    asm("{ .reg .u64 t; cvta.to.shared.u64 t, %1; cvt.u32.u64 %0, t; }" : "=r"(a) : "l"(p));
    return a;
}
// 128B rows, 8 x 16B chunks per row; chunk XOR row&7 keeps both the 16B store
// phases and all ldmatrix read phases bank-conflict-free (validated round 6).
__device__ __forceinline__ uint32_t swz8(uint32_t row, uint32_t q) {
    return row * 128u + ((q ^ (row & 7u)) << 4);
}
__device__ __forceinline__ void cpa16(uint32_t dst, const void* src) {
    asm volatile("cp.async.cg.shared.global [%0], [%1], 16;" :: "r"(dst), "l"(src) : "memory");
}
__device__ __forceinline__ void mbar_init(uint32_t mbar, uint32_t cnt) {
    asm volatile("mbarrier.init.shared.b64 [%0], %1;" :: "r"(mbar), "r"(cnt) : "memory");
}
__device__ __forceinline__ void mbar_arrive(uint32_t mbar) {
    asm volatile("mbarrier.arrive.shared.b64 _, [%0];" :: "r"(mbar) : "memory");
}
// .noinc: consumes one pre-initialized arrival slot on async completion (the
// default form pre-increments the expected count and is net-zero -> deadlock).
__device__ __forceinline__ void cp_arrive_noinc(uint32_t mbar) {
    asm volatile("cp.async.mbarrier.arrive.noinc.shared::cta.b64 [%0];" :: "r"(mbar) : "memory");
}
__device__ __forceinline__ void mbar_wait(uint32_t mbar, uint32_t phase) {
    asm volatile(
        "{\n\t.reg .pred P;\n\t"
        "W%=:\n\t"
        "mbarrier.try_wait.parity.acquire.cta.shared::cta.b64 P, [%0], %1, 0x989680;\n\t"
        "@!P bra W%=;\n\t}"
        :: "r"(mbar), "r"(phase) : "memory");
}
__device__ __forceinline__ void ldsm4(uint32_t* r, uint32_t addr) {
    asm volatile("ldmatrix.sync.aligned.m8n8.x4.shared.b16 {%0,%1,%2,%3}, [%4];"
        : "=r"(r[0]), "=r"(r[1]), "=r"(r[2]), "=r"(r[3]) : "r"(addr));
}
__device__ __forceinline__ void ldsm2(uint32_t* r, uint32_t addr) {
    asm volatile("ldmatrix.sync.aligned.m8n8.x2.shared.b16 {%0,%1}, [%2];"
        : "=r"(r[0]), "=r"(r[1]) : "r"(addr));
}
__device__ __forceinline__ void mma16816(float* c, const uint32_t* a, const uint32_t* b) {
    asm volatile(
        "mma.sync.aligned.m16n8k16.row.col.f32.f16.f16.f32 "
        "{%0,%1,%2,%3}, {%4,%5,%6,%7}, {%8,%9}, {%0,%1,%2,%3};"
        : "+f"(c[0]), "+f"(c[1]), "+f"(c[2]), "+f"(c[3])
        : "r"(a[0]), "r"(a[1]), "r"(a[2]), "r"(a[3]), "r"(b[0]), "r"(b[1]));
}
__device__ __forceinline__ uint32_t packh2(float lo, float hi) {
    uint32_t r;
    asm("cvt.rn.f16x2.f32 %0, %1, %2;" : "=r"(r) : "f"(hi), "f"(lo));
    return r;
}

// ---------------- W fp32 -> fp16 pre-kernel (rows >= 405 zeroed) ----------------
__global__ void wconv_kernel(const float* __restrict__ Wc, const float* __restrict__ Wr) {
    int row = blockIdx.y;
    int col = (blockIdx.x * 256 + threadIdx.x) * 4;
    if (col >= KDIM) return;
    float4 v = make_float4(0.f, 0.f, 0.f, 0.f);
    if (row < NCLS)      v = *reinterpret_cast<const float4*>(Wc + (size_t)row * KDIM + col);
    else if (row < NTOT) v = *reinterpret_cast<const float4*>(Wr + (size_t)(row - NCLS) * KDIM + col);
    *reinterpret_cast<uint2*>(&g_Wh[(size_t)row * KDIM + col]) =
        make_uint2(packh2(v.x, v.y), packh2(v.z, v.w));
}

// ---------------- main GEMM kernel ----------------
__global__ __launch_bounds__(NTHREADS, 1)
void bbox_head_mma(const float* __restrict__ A,
                   const float* __restrict__ bc,
                   const float* __restrict__ br,
                   float* __restrict__ out)
{
    extern __shared__ char smem[];
    const uint32_t sb = smem_u32(smem);
    const int tid   = threadIdx.x;
    const int lane  = tid & 31;
    const int wid   = tid >> 5;
    const int warpM = wid & 1;          // 0..1  (32-row halves of BM=64)
    const int warpN = wid >> 1;         // 0..7  (56-col slices of NPAD=448)
    const int mBlock = blockIdx.x * BM;
    float* bias_sm = reinterpret_cast<float*>(smem + OFF_BIAS);

#define FULLB(s)  (sb + OFF_MBAR + (s) * 8)
#define EMPTYB(s) (sb + OFF_MBAR + NSTAGE * 8 + (s) * 8)

    if (tid == 0) {
        #pragma unroll
        for (int s = 0; s < NSTAGE; s++) {
            mbar_init(FULLB(s), 2 * NTHREADS);  // 512 STS-arrives + 512 noinc cp-arrives
            mbar_init(EMPTYB(s), NTHREADS);
        }
    }
    for (int j = tid; j < NPAD; j += NTHREADS)
        bias_sm[j] = (j < NCLS) ? bc[j] : ((j < NTOT) ? br[j - NCLS] : 0.f);
    __syncthreads();

    // A loader: thread owns row (tid>>3), 16B chunk q (tid&7)
    const int ar = tid >> 3;            // 0..63
    const int aq = tid & 7;             // 0..7
    float4 abuf0, abuf1;

    float acc[2][7][4];
    #pragma unroll
    for (int i = 0; i < 2; i++)
        #pragma unroll
        for (int j = 0; j < 7; j++)
            #pragma unroll
            for (int v = 0; v < 4; v++) acc[i][j][v] = 0.f;

#define LDG_A(K0) do { \
        const float* _p = A + (size_t)(mBlock + ar) * KDIM + (K0) + aq * 8; \
        abuf0 = *reinterpret_cast<const float4*>(_p); \
        abuf1 = *reinterpret_cast<const float4*>(_p + 4); } while (0)

#define STS_A(S) do { \
        uint4 _v = make_uint4(packh2(abuf0.x, abuf0.y), packh2(abuf0.z, abuf0.w), \
                              packh2(abuf1.x, abuf1.y), packh2(abuf1.z, abuf1.w)); \
        *reinterpret_cast<uint4*>(smem + OFF_A + (S) * A_STAGE + swz8(ar, aq)) = _v; } while (0)

#define CP_B(K0, S) do { \
        _Pragma("unroll") \
        for (int _i = 0; _i < 7; _i++) { \
            int _idx = tid + _i * NTHREADS; /* 0..3583 = 448 rows x 8 chunks */ \
            int _row = _idx >> 3, _q = _idx & 7; \
            cpa16(sb + OFF_B + (S) * B_STAGE + swz8(_row, _q), \
                  g_Wh + (size_t)_row * KDIM + (K0) + _q * 8); } } while (0)

    // ---- prologue: produce stages 0,1; hold chunk 2's A in regs ----
    LDG_A(0);
    STS_A(0); CP_B(0, 0); mbar_arrive(FULLB(0)); cp_arrive_noinc(FULLB(0));
    LDG_A(BK);
    STS_A(1); CP_B(BK, 1); mbar_arrive(FULLB(1)); cp_arrive_noinc(FULLB(1));
    LDG_A(2 * BK);

    // ---- main loop: consume chunk k, produce chunk k+2 ----
    for (int k = 0; k < NCHUNK; k++) {
        const int sc = k % NSTAGE;
        mbar_wait(FULLB(sc), (uint32_t)((k / NSTAGE) & 1));

        const uint32_t aS = sb + OFF_A + sc * A_STAGE;
        const uint32_t bS = sb + OFF_B + sc * B_STAGE;

        #pragma unroll
        for (int kt = 0; kt < 4; kt++) {
            uint32_t afrag[2][4];
            #pragma unroll
            for (int msub = 0; msub < 2; msub++) {
                uint32_t row = warpM * 32 + msub * 16 + ((lane >> 3) & 1) * 8 + (lane & 7);
                uint32_t q   = kt * 2 + (lane >> 4);
                ldsm4(afrag[msub], aS + swz8(row, q));
            }
            uint32_t bfrag[7][2];
            #pragma unroll
            for (int p = 0; p < 3; p++) {
                uint32_t row = warpN * 56 + p * 16 + (lane >> 4) * 8 + (lane & 7);
                uint32_t q   = kt * 2 + ((lane >> 3) & 1);
                uint32_t r4[4];
                ldsm4(r4, bS + swz8(row, q));
                bfrag[2 * p][0] = r4[0]; bfrag[2 * p][1] = r4[1];
                bfrag[2 * p + 1][0] = r4[2]; bfrag[2 * p + 1][1] = r4[3];
            }
            {
                uint32_t row = warpN * 56 + 48 + (lane & 7);
                uint32_t q   = kt * 2 + ((lane >> 3) & 1);
                ldsm2(bfrag[6], bS + swz8(row, q));
            }
            #pragma unroll
            for (int mi = 0; mi < 2; mi++)
                #pragma unroll
                for (int ni = 0; ni < 7; ni++)
                    mma16816(acc[mi][ni], afrag[mi], bfrag[ni]);
        }
        mbar_arrive(EMPTYB(sc));

        const int j = k + 2;
        if (j < NCHUNK) {
            const int sp = j % NSTAGE;
            // stage sp's previous content is chunk j-NSTAGE; wait for the
            // (j/NSTAGE)-th EMPTY completion -> parity ((j/NSTAGE)&1)^1
            mbar_wait(EMPTYB(sp), (uint32_t)(((j / NSTAGE) & 1) ^ 1));
            STS_A(sp);
            CP_B(j * BK, sp);
            mbar_arrive(FULLB(sp));        // release for the STS
            cp_arrive_noinc(FULLB(sp));    // fires when this thread's cp.asyncs land
            if (j + 1 < NCHUNK) LDG_A((j + 1) * BK);
        }
    }

    // ---- epilogue: bias + split store ----
    const size_t regBase = (size_t)MDIM * NCLS;
    #pragma unroll
    for (int mi = 0; mi < 2; mi++) {
        #pragma unroll
        for (int ni = 0; ni < 7; ni++) {
            int m0 = mBlock + warpM * 32 + mi * 16 + (lane >> 2);
            int n0 = warpN * 56 + ni * 8 + (lane & 3) * 2;
            #pragma unroll
            for (int v = 0; v < 4; v++) {
                int m = m0 + (v >> 1) * 8;
                int n = n0 + (v & 1);
                if (n >= NTOT) continue;
                float val = acc[mi][ni][v] + bias_sm[n];
                if (n < NCLS) out[(size_t)m * NCLS + n] = val;
                else          out[regBase + (size_t)m * NREG + (n - NCLS)] = val;
            }
        }
    }
}

extern "C" void kernel_launch(void* const* d_in, const int* in_sizes, int n_in,
                              void* d_out, int out_size)
{
    const float* x  = (const float*)d_in[0];
    const float* Wc = (const float*)d_in[1];
    const float* bc = (const float*)d_in[2];
    const float* Wr = (const float*)d_in[3];
    const float* br = (const float*)d_in[4];
    float* out = (float*)d_out;

    cudaFuncSetAttribute(bbox_head_mma, cudaFuncAttributeMaxDynamicSharedMemorySize, SMEM_TOTAL);

    dim3 wgrid((KDIM / 4 + 255) / 256, NPAD);
    wconv_kernel<<<wgrid, 256>>>(Wc, Wr);

    bbox_head_mma<<<MDIM / BM, NTHREADS, SMEM_TOTAL>>>(x, bc, br, out);
}

// round 11
// speedup vs baseline: 1.5969x; 1.0604x over previous
#include <cuda_runtime.h>
#include <cuda_fp16.h>
#include <cstdint>

// ============================================================================
// BBoxHead as one fp16 legacy-HMMA GEMM (mma.sync.m16n8k16; compute_103 target
// has no tcgen05). C[8192,448] = A[8192,12544] x W[448,12544]^T, fp32 acc.
//   cols 0..80   -> cls head (+b_cls):  out[m*81 + n]
//   cols 81..404 -> reg head (+b_reg):  out[8192*81 + m*324 + (n-81)]
//   cols 405..447 = zero pad (discarded)
// Round-11 vs round-10 (248us, tensor 63%, L1 65%): cut the smem floor below
// the tensor floor and hide LDS latency in-warp:
//   (1) 8 warps 1Mx8N (warp tile 64x56): B rows single-owner -> smem reads
//       176KB -> 120KB per chunk (~1440 cyc < 1792 tensor floor).
//   (2) intra-chunk fragment double-buffering (load kt+1 frags during kt MMAs);
//       256 threads -> 255-reg cap, ~205 regs, no spill.
// Keeps the round-10 validated 3-stage mbarrier full/empty pipeline (cp.async
// completion via .noinc arrive) and the XOR-8 swizzle.
// ============================================================================

#define KDIM  12544
#define MDIM  8192
#define NCLS  81
#define NREG  324
#define NTOT  405
#define NPAD  448
#define BM    64
#define BK    64
#define NCHUNK 196            // 12544 / 64
#define NSTAGE 3
#define NTHREADS 256

#define A_STAGE 8192          // 64 rows x 128B
#define B_STAGE 57344         // 448 rows x 128B
#define OFF_BIAS 0            // 448 * 4 = 1792B
#define OFF_MBAR 1792         // 6 mbarriers x 8B
#define OFF_A    2048
#define OFF_B    (OFF_A + NSTAGE * A_STAGE)   // 26624
#define SMEM_TOTAL (OFF_B + NSTAGE * B_STAGE) // 198656

__device__ __half g_Wh[(size_t)NPAD * KDIM];  // 11.2 MB fp16 W scratch

// ---------------- helpers ----------------
__device__ __forceinline__ uint32_t smem_u32(const void* p) {
    uint32_t a;
    asm("{ .reg .u64 t; cvta.to.shared.u64 t, %1; cvt.u32.u64 %0, t; }" : "=r"(a) : "l"(p));
    return a;
}
// 128B rows, 8 x 16B chunks per row; chunk XOR row&7 keeps both the 16B store
// phases and all ldmatrix read phases bank-conflict-free (validated round 6/10).
__device__ __forceinline__ uint32_t swz8(uint32_t row, uint32_t q) {
    return row * 128u + ((q ^ (row & 7u)) << 4);
}
__device__ __forceinline__ void cpa16(uint32_t dst, const void* src) {
    asm volatile("cp.async.cg.shared.global [%0], [%1], 16;" :: "r"(dst), "l"(src) : "memory");
}
__device__ __forceinline__ void mbar_init(uint32_t mbar, uint32_t cnt) {
    asm volatile("mbarrier.init.shared.b64 [%0], %1;" :: "r"(mbar), "r"(cnt) : "memory");
}
__device__ __forceinline__ void mbar_arrive(uint32_t mbar) {
    asm volatile("mbarrier.arrive.shared.b64 _, [%0];" :: "r"(mbar) : "memory");
}
// .noinc: consumes one pre-initialized arrival slot on async completion.
__device__ __forceinline__ void cp_arrive_noinc(uint32_t mbar) {
    asm volatile("cp.async.mbarrier.arrive.noinc.shared::cta.b64 [%0];" :: "r"(mbar) : "memory");
}
__device__ __forceinline__ void mbar_wait(uint32_t mbar, uint32_t phase) {
    asm volatile(
        "{\n\t.reg .pred P;\n\t"
        "W%=:\n\t"
        "mbarrier.try_wait.parity.acquire.cta.shared::cta.b64 P, [%0], %1, 0x989680;\n\t"
        "@!P bra W%=;\n\t}"
        :: "r"(mbar), "r"(phase) : "memory");
}
__device__ __forceinline__ void ldsm4(uint32_t* r, uint32_t addr) {
    asm volatile("ldmatrix.sync.aligned.m8n8.x4.shared.b16 {%0,%1,%2,%3}, [%4];"
        : "=r"(r[0]), "=r"(r[1]), "=r"(r[2]), "=r"(r[3]) : "r"(addr));
}
__device__ __forceinline__ void ldsm2(uint32_t* r, uint32_t addr) {
    asm volatile("ldmatrix.sync.aligned.m8n8.x2.shared.b16 {%0,%1}, [%2];"
        : "=r"(r[0]), "=r"(r[1]) : "r"(addr));
}
__device__ __forceinline__ void mma16816(float* c, const uint32_t* a, const uint32_t* b) {
    asm volatile(
        "mma.sync.aligned.m16n8k16.row.col.f32.f16.f16.f32 "
        "{%0,%1,%2,%3}, {%4,%5,%6,%7}, {%8,%9}, {%0,%1,%2,%3};"
        : "+f"(c[0]), "+f"(c[1]), "+f"(c[2]), "+f"(c[3])
        : "r"(a[0]), "r"(a[1]), "r"(a[2]), "r"(a[3]), "r"(b[0]), "r"(b[1]));
}
__device__ __forceinline__ uint32_t packh2(float lo, float hi) {
    uint32_t r;
    asm("cvt.rn.f16x2.f32 %0, %1, %2;" : "=r"(r) : "f"(hi), "f"(lo));
    return r;
}

// ---------------- W fp32 -> fp16 pre-kernel (rows >= 405 zeroed) ----------------
__global__ void wconv_kernel(const float* __restrict__ Wc, const float* __restrict__ Wr) {
    int row = blockIdx.y;
    int col = (blockIdx.x * 256 + threadIdx.x) * 4;
    if (col >= KDIM) return;
    float4 v = make_float4(0.f, 0.f, 0.f, 0.f);
    if (row < NCLS)      v = *reinterpret_cast<const float4*>(Wc + (size_t)row * KDIM + col);
    else if (row < NTOT) v = *reinterpret_cast<const float4*>(Wr + (size_t)(row - NCLS) * KDIM + col);
    *reinterpret_cast<uint2*>(&g_Wh[(size_t)row * KDIM + col]) =
        make_uint2(packh2(v.x, v.y), packh2(v.z, v.w));
}

// ---------------- main GEMM kernel ----------------
__global__ __launch_bounds__(NTHREADS, 1)
void bbox_head_mma(const float* __restrict__ A,
                   const float* __restrict__ bc,
                   const float* __restrict__ br,
                   float* __restrict__ out)
{
    extern __shared__ char smem[];
    const uint32_t sb = smem_u32(smem);
    const int tid   = threadIdx.x;
    const int lane  = tid & 31;
    const int warpN = tid >> 5;         // 0..7, 56-col slice of NPAD=448
    const int mBlock = blockIdx.x * BM;
    float* bias_sm = reinterpret_cast<float*>(smem + OFF_BIAS);

#define FULLB(s)  (sb + OFF_MBAR + (s) * 8)
#define EMPTYB(s) (sb + OFF_MBAR + NSTAGE * 8 + (s) * 8)

    if (tid == 0) {
        #pragma unroll
        for (int s = 0; s < NSTAGE; s++) {
            mbar_init(FULLB(s), 2 * NTHREADS);  // 256 STS-arrives + 256 noinc cp-arrives
            mbar_init(EMPTYB(s), NTHREADS);
        }
    }
    for (int j = tid; j < NPAD; j += NTHREADS)
        bias_sm[j] = (j < NCLS) ? bc[j] : ((j < NTOT) ? br[j - NCLS] : 0.f);
    __syncthreads();

    // A loader: thread owns row (tid>>2), 16B chunks aq, aq+1 (aq=(tid&3)*2)
    const int ar = tid >> 2;            // 0..63
    const int aq = (tid & 3) * 2;       // 0,2,4,6
    float4 abuf[4];

    float acc[4][7][4];
    #pragma unroll
    for (int i = 0; i < 4; i++)
        #pragma unroll
        for (int j = 0; j < 7; j++)
            #pragma unroll
            for (int v = 0; v < 4; v++) acc[i][j][v] = 0.f;

#define LDG_A(K0) do { \
        const float* _p = A + (size_t)(mBlock + ar) * KDIM + (K0) + aq * 8; \
        abuf[0] = *reinterpret_cast<const float4*>(_p); \
        abuf[1] = *reinterpret_cast<const float4*>(_p + 4); \
        abuf[2] = *reinterpret_cast<const float4*>(_p + 8); \
        abuf[3] = *reinterpret_cast<const float4*>(_p + 12); } while (0)

#define STS_A(S) do { \
        uint4 _v0 = make_uint4(packh2(abuf[0].x, abuf[0].y), packh2(abuf[0].z, abuf[0].w), \
                               packh2(abuf[1].x, abuf[1].y), packh2(abuf[1].z, abuf[1].w)); \
        uint4 _v1 = make_uint4(packh2(abuf[2].x, abuf[2].y), packh2(abuf[2].z, abuf[2].w), \
                               packh2(abuf[3].x, abuf[3].y), packh2(abuf[3].z, abuf[3].w)); \
        *reinterpret_cast<uint4*>(smem + OFF_A + (S) * A_STAGE + swz8(ar, aq)) = _v0; \
        *reinterpret_cast<uint4*>(smem + OFF_A + (S) * A_STAGE + swz8(ar, aq + 1)) = _v1; } while (0)

#define CP_B(K0, S) do { \
        _Pragma("unroll") \
        for (int _i = 0; _i < 14; _i++) { \
            int _idx = tid + _i * NTHREADS; /* 0..3583 = 448 rows x 8 chunks */ \
            int _row = _idx >> 3, _q = _idx & 7; \
            cpa16(sb + OFF_B + (S) * B_STAGE + swz8(_row, _q), \
                  g_Wh + (size_t)_row * KDIM + (K0) + _q * 8); } } while (0)

    // fragment load for one kt (0..3) into given buffers
#define LOAD_FRAGS(KT, AF, BF) do { \
        _Pragma("unroll") \
        for (int _m = 0; _m < 4; _m++) { \
            uint32_t _row = _m * 16 + ((lane >> 3) & 1) * 8 + (lane & 7); \
            uint32_t _q   = (KT) * 2 + (lane >> 4); \
            ldsm4((AF)[_m], aS + swz8(_row, _q)); } \
        _Pragma("unroll") \
        for (int _p = 0; _p < 3; _p++) { \
            uint32_t _row = warpN * 56 + _p * 16 + (lane >> 4) * 8 + (lane & 7); \
            uint32_t _q   = (KT) * 2 + ((lane >> 3) & 1); \
            uint32_t _r4[4]; \
            ldsm4(_r4, bS + swz8(_row, _q)); \
            (BF)[2 * _p][0] = _r4[0]; (BF)[2 * _p][1] = _r4[1]; \
            (BF)[2 * _p + 1][0] = _r4[2]; (BF)[2 * _p + 1][1] = _r4[3]; } \
        { uint32_t _row = warpN * 56 + 48 + (lane & 7); \
          uint32_t _q   = (KT) * 2 + ((lane >> 3) & 1); \
          ldsm2((BF)[6], bS + swz8(_row, _q)); } } while (0)

    // ---- prologue: produce stages 0,1; hold chunk 2's A in regs ----
    LDG_A(0);
    STS_A(0); CP_B(0, 0); mbar_arrive(FULLB(0)); cp_arrive_noinc(FULLB(0));
    LDG_A(BK);
    STS_A(1); CP_B(BK, 1); mbar_arrive(FULLB(1)); cp_arrive_noinc(FULLB(1));
    LDG_A(2 * BK);

    // ---- main loop: consume chunk k (double-buffered frags), produce k+2 ----
    for (int k = 0; k < NCHUNK; k++) {
        const int sc = k % NSTAGE;
        mbar_wait(FULLB(sc), (uint32_t)((k / NSTAGE) & 1));

        const uint32_t aS = sb + OFF_A + sc * A_STAGE;
        const uint32_t bS = sb + OFF_B + sc * B_STAGE;

        uint32_t afrag[2][4][4];
        uint32_t bfrag[2][7][2];
        LOAD_FRAGS(0, afrag[0], bfrag[0]);
        #pragma unroll
        for (int kt = 0; kt < 4; kt++) {
            const int cur = kt & 1, nxt = cur ^ 1;
            if (kt < 3) LOAD_FRAGS(kt + 1, afrag[nxt], bfrag[nxt]);
            #pragma unroll
            for (int mi = 0; mi < 4; mi++)
                #pragma unroll
                for (int ni = 0; ni < 7; ni++)
                    mma16816(acc[mi][ni], afrag[cur][mi], bfrag[cur][ni]);
        }
        mbar_arrive(EMPTYB(sc));

        const int j = k + 2;
        if (j < NCHUNK) {
            const int sp = j % NSTAGE;
            mbar_wait(EMPTYB(sp), (uint32_t)(((j / NSTAGE) & 1) ^ 1));
            STS_A(sp);
            CP_B(j * BK, sp);
            mbar_arrive(FULLB(sp));        // release for the STS
            cp_arrive_noinc(FULLB(sp));    // fires when this thread's cp.asyncs land
            if (j + 1 < NCHUNK) LDG_A((j + 1) * BK);
        }
    }

    // ---- epilogue: bias + split store ----
    const size_t regBase = (size_t)MDIM * NCLS;
    #pragma unroll
    for (int mi = 0; mi < 4; mi++) {
        #pragma unroll
        for (int ni = 0; ni < 7; ni++) {
            int m0 = mBlock + mi * 16 + (lane >> 2);
            int n0 = warpN * 56 + ni * 8 + (lane & 3) * 2;
            #pragma unroll
            for (int v = 0; v < 4; v++) {
                int m = m0 + (v >> 1) * 8;
                int n = n0 + (v & 1);
                if (n >= NTOT) continue;
                float val = acc[mi][ni][v] + bias_sm[n];
                if (n < NCLS) out[(size_t)m * NCLS + n] = val;
                else          out[regBase + (size_t)m * NREG + (n - NCLS)] = val;
            }
        }
    }
}

extern "C" void kernel_launch(void* const* d_in, const int* in_sizes, int n_in,
                              void* d_out, int out_size)
{
    const float* x  = (const float*)d_in[0];
    const float* Wc = (const float*)d_in[1];
    const float* bc = (const float*)d_in[2];
    const float* Wr = (const float*)d_in[3];
    const float* br = (const float*)d_in[4];
    float* out = (float*)d_out;

    cudaFuncSetAttribute(bbox_head_mma, cudaFuncAttributeMaxDynamicSharedMemorySize, SMEM_TOTAL);

    dim3 wgrid((KDIM / 4 + 255) / 256, NPAD);
    wconv_kernel<<<wgrid, 256>>>(Wc, Wr);

    bbox_head_mma<<<MDIM / BM, NTHREADS, SMEM_TOTAL>>>(x, bc, br, out);
}